// round 6
// baseline (speedup 1.0000x reference)
#include <cuda_runtime.h>

// ---------------------------------------------------------------------------
// EnhancedReconstructionLoss: 0.8*MSE + 0.2*(1 - mean(SSIM_map)), fused.
//
// s/d reformulation (s=x+y, d=x-y) -> 4 window sums (Ws,Wd,Wss,Wdd):
//   N1 = (Ws^2-Wd^2) + 162*C1          N2 = 9(Wss-Wdd) - (Ws^2-Wd^2) + 162*C2
//   D1 = (Ws^2+Wd^2) + 162*C1          D2 = 9(Wss+Wdd) - (Ws^2+Wd^2) + 162*C2
//   ssim = N1*N2 / (D1*D2 + 4*6561*eps)
//
// R6: cp.async (LDGSTS) smem staging, 4-stage per-warp ring, prefetch
// distance 2; register window stays 3-slot s/d. Zero registers spent on
// in-flight data -> 5 CTAs/SM AND deep latency cover simultaneously.
// Per-lane XOR-swizzled 16B units: conflict-free, no padding, and each lane
// reads only bytes it copied itself (no __syncwarp needed).
// ---------------------------------------------------------------------------

typedef unsigned long long u64;
typedef unsigned int u32;

#define IMW 512
#define IMH 512
#define NPLANES 96
#define RPW 16                    // rows per warp-task
#define STRIPS 32                 // 512 / 16
#define WPB 4                     // warps per block
#define NBLOCKS (NPLANES * STRIPS * 2 / WPB)   // 1536
#define NTOTD 25165824.0          // 32*3*512*512

#define NSTG 4                    // smem pipeline stages per warp
#define STGB 2064                 // bytes per stage: x 1024 + y 1024 + halo 8 + pad

__device__ float g_mse_acc  = 0.f;
__device__ float g_ssim_acc = 0.f;
__device__ unsigned int g_cnt = 0u;

__device__ __forceinline__ u64 f2_pack(float lo, float hi) {
    u64 r; asm("mov.b64 %0, {%1, %2};" : "=l"(r) : "f"(lo), "f"(hi)); return r;
}
__device__ __forceinline__ void f2_unpack(u64 p, float& lo, float& hi) {
    asm("mov.b64 {%0, %1}, %2;" : "=f"(lo), "=f"(hi) : "l"(p));
}
__device__ __forceinline__ u64 f2_set(float v) { return f2_pack(v, v); }
__device__ __forceinline__ u64 add2(u64 a, u64 b) {
    u64 d; asm("add.rn.f32x2 %0, %1, %2;" : "=l"(d) : "l"(a), "l"(b)); return d;
}
__device__ __forceinline__ u64 mul2(u64 a, u64 b) {
    u64 d; asm("mul.rn.f32x2 %0, %1, %2;" : "=l"(d) : "l"(a), "l"(b)); return d;
}
__device__ __forceinline__ u64 fma2(u64 a, u64 b, u64 c) {
    u64 d; asm("fma.rn.f32x2 %0, %1, %2, %3;" : "=l"(d) : "l"(a), "l"(b), "l"(c)); return d;
}

__device__ __forceinline__ void cp16(u32 dst, const void* src, int sz) {
    asm volatile("cp.async.cg.shared.global [%0], [%1], 16, %2;"
                 :: "r"(dst), "l"(src), "r"(sz) : "memory");
}
__device__ __forceinline__ void cp4(u32 dst, const void* src, int sz) {
    asm volatile("cp.async.ca.shared.global [%0], [%1], 4, %2;"
                 :: "r"(dst), "l"(src), "r"(sz) : "memory");
}
__device__ __forceinline__ void cp_commit() {
    asm volatile("cp.async.commit_group;" ::: "memory");
}
template <int N>
__device__ __forceinline__ void cp_wait() {
    asm volatile("cp.async.wait_group %0;" :: "n"(N) : "memory");
}

// Horizontal 3-sum over 8 columns (4 packed u64), warp-shuffle neighbors plus
// scalar halo vH at the warp's interior boundary.
__device__ __forceinline__ void hsum8(const u64 v0, const u64 v1, const u64 v2, const u64 v3,
                                      float vH, int lane, int half,
                                      u64& H0, u64& H1, u64& H2, u64& H3) {
    float f0, f1, f2, f3, f4, f5, f6, f7;
    f2_unpack(v0, f0, f1);
    f2_unpack(v1, f2, f3);
    f2_unpack(v2, f4, f5);
    f2_unpack(v3, f6, f7);
    float up = __shfl_up_sync(0xffffffffu, f7, 1);
    float dn = __shfl_down_sync(0xffffffffu, f0, 1);
    float nl = (lane == 0)  ? (half ? vH : 0.f) : up;
    float nr = (lane == 31) ? (half ? 0.f : vH) : dn;
    u64 L0 = f2_pack(nl, f0);
    u64 L1 = f2_pack(f1, f2);
    u64 L2 = f2_pack(f3, f4);
    u64 L3 = f2_pack(f5, f6);
    u64 R3 = f2_pack(f7, nr);
    H0 = add2(add2(L0, v0), L1);
    H1 = add2(add2(L1, v1), L2);
    H2 = add2(add2(L2, v2), L3);
    H3 = add2(add2(L3, v3), R3);
}

__global__ void __launch_bounds__(128, 5)
loss_fused(const float* __restrict__ X, const float* __restrict__ Y,
           float* __restrict__ out) {
    __shared__ char stg[WPB * NSTG * STGB];   // 33 KB

    const int w    = threadIdx.x >> 5;
    const int lane = threadIdx.x & 31;
    const int task  = blockIdx.x * WPB + w;
    const int half  = task & 1;
    const int strip = (task >> 1) & (STRIPS - 1);
    const int plane = task >> 6;
    const int R0 = strip * RPW;

    // Warp-level base pointers (cols [half*256, half*256+256)).
    const float* pxw = X + (size_t)plane * (IMW * IMH) + half * 256;
    const float* pyw = Y + (size_t)plane * (IMW * IMH) + half * 256;

    // halo: half==0 -> col 256 (read by lane 31); half==1 -> col 255 (lane 0).
    const bool hduty = half ? (lane == 0) : (lane == 31);
    const int  hoffw = half ? -1 : 256;

    // XOR-swizzled 16B-unit offsets for this lane's 32B chunk (conflict-free
    // for both the paired LDS.128 reads and the async stores).
    const int swz = (lane >> 2) & 1;
    const u32 offA = 16u * (u32)((2 * lane)     ^ swz);
    const u32 offB = 16u * (u32)((2 * lane + 1) ^ swz);

    const u32  warp_base_u32 = (u32)__cvta_generic_to_shared(stg) + (u32)(w * NSTG * STGB);
    char* const warp_base_c  = stg + w * NSTG * STGB;

    const u64 km1  = f2_set(-1.0f);
    const u64 k9   = f2_set(9.0f);
    const u64 kC1  = f2_set(0.0162f);      // 162 * C1
    const u64 kC2  = f2_set(0.1458f);      // 162 * C2
    const u64 kEPS = f2_set(2.6244e-4f);   // 4 * 6561 * eps

    // 3-slot rolling register window of s,d rows + halo scalars.
    u64 ws[3][4], wdv[3][4];
    float whs[3], whd[3];

    // Issue async copy of window row j (global row R0-1+j) into stage j%4.
    auto ISSUE = [&](int j) {
        const int gr = R0 - 1 + j;
        const bool v = ((unsigned)gr < (unsigned)IMH);
        const int sz = v ? 16 : 0;
        const int grc = v ? gr : 0;
        const float* sx = pxw + (size_t)grc * IMW + (lane << 3);
        const float* sy = pyw + (size_t)grc * IMW + (lane << 3);
        const u32 b = warp_base_u32 + (u32)((j & 3) * STGB);
        cp16(b + offA, sx, sz);
        cp16(b + offB, sx + 4, sz);
        cp16(b + 1024 + offA, sy, sz);
        cp16(b + 1024 + offB, sy + 4, sz);
        if (hduty) {
            const int s4 = v ? 4 : 0;
            cp4(b + 2048, pxw + (size_t)grc * IMW + hoffw, s4);
            cp4(b + 2052, pyw + (size_t)grc * IMW + hoffw, s4);
        }
        cp_commit();
    };

    // Convert staged row j into window slot j%3.
    auto CONVERT = [&](int j) {
        const int slot = j % 3;
        char* b = warp_base_c + (j & 3) * STGB;
        float4 xa = *reinterpret_cast<const float4*>(b + offA);
        float4 xb = *reinterpret_cast<const float4*>(b + offB);
        float4 ya = *reinterpret_cast<const float4*>(b + 1024 + offA);
        float4 yb = *reinterpret_cast<const float4*>(b + 1024 + offB);
        float hx = *reinterpret_cast<const float*>(b + 2048);
        float hy = *reinterpret_cast<const float*>(b + 2052);
        u64 xp0 = f2_pack(xa.x, xa.y), xp1 = f2_pack(xa.z, xa.w);
        u64 xp2 = f2_pack(xb.x, xb.y), xp3 = f2_pack(xb.z, xb.w);
        u64 yp0 = f2_pack(ya.x, ya.y), yp1 = f2_pack(ya.z, ya.w);
        u64 yp2 = f2_pack(yb.x, yb.y), yp3 = f2_pack(yb.z, yb.w);
        ws[slot][0] = add2(xp0, yp0);   wdv[slot][0] = fma2(yp0, km1, xp0);
        ws[slot][1] = add2(xp1, yp1);   wdv[slot][1] = fma2(yp1, km1, xp1);
        ws[slot][2] = add2(xp2, yp2);   wdv[slot][2] = fma2(yp2, km1, xp2);
        ws[slot][3] = add2(xp3, yp3);   wdv[slot][3] = fma2(yp3, km1, xp3);
        whs[slot] = hx + hy;
        whd[slot] = hx - hy;
    };

    // Prologue: rows 0..3 in flight; convert rows 0,1.
    ISSUE(0); ISSUE(1); ISSUE(2); ISSUE(3);
    cp_wait<2>();            // rows 0,1 complete
    CONVERT(0); CONVERT(1);

    u64 mAcc0 = f2_set(0.f), mAcc1 = f2_set(0.f);
    float sAcc = 0.f;

#pragma unroll
    for (int r = 0; r < RPW; ++r) {
        if (r + 4 <= RPW + 1) ISSUE(r + 4);
        else                  cp_commit();     // keep group accounting uniform
        cp_wait<2>();                          // row r+2 complete
        CONVERT(r + 2);

        const int j0 = r % 3, j1 = (r + 1) % 3, j2 = (r + 2) % 3;

        // halo vertical sums (consumed only by the duty lane)
        float hs0 = whs[j0], hs1 = whs[j1], hs2 = whs[j2];
        float hd0 = whd[j0], hd1 = whd[j1], hd2 = whd[j2];
        float vHs  = hs0 + hs1 + hs2;
        float vHd  = hd0 + hd1 + hd2;
        float vHss = fmaf(hs0, hs0, fmaf(hs1, hs1, hs2 * hs2));
        float vHdd = fmaf(hd0, hd0, fmaf(hd1, hd1, hd2 * hd2));

        // ---- Ws, Wd first; derive T1/T2; release transients early ----
        u64 T1[4], T2[4];
        {
            u64 Vq[4], Hq[4];
#pragma unroll
            for (int k = 0; k < 4; ++k)
                Vq[k] = add2(add2(ws[j0][k], ws[j1][k]), ws[j2][k]);
            hsum8(Vq[0], Vq[1], Vq[2], Vq[3], vHs, lane, half,
                  Hq[0], Hq[1], Hq[2], Hq[3]);
            u64 Es[4];
#pragma unroll
            for (int k = 0; k < 4; ++k) Es[k] = mul2(Hq[k], Hq[k]);   // Ws^2
#pragma unroll
            for (int k = 0; k < 4; ++k)
                Vq[k] = add2(add2(wdv[j0][k], wdv[j1][k]), wdv[j2][k]);
            hsum8(Vq[0], Vq[1], Vq[2], Vq[3], vHd, lane, half,
                  Hq[0], Hq[1], Hq[2], Hq[3]);
#pragma unroll
            for (int k = 0; k < 4; ++k) {
                u64 F = mul2(Hq[k], Hq[k]);            // Wd^2
                T1[k] = fma2(F, km1, Es[k]);           // Ws^2 - Wd^2
                T2[k] = add2(Es[k], F);                // Ws^2 + Wd^2
            }
        }

        // ---- Wss, Wdd; finish the rational ----
        {
            u64 Vss[4], Vdd[4], Hss[4], Hdd[4];
#pragma unroll
            for (int k = 0; k < 4; ++k) {
                u64 s0 = ws[j0][k], s1 = ws[j1][k], s2 = ws[j2][k];
                u64 d0 = wdv[j0][k], d1 = wdv[j1][k], d2 = wdv[j2][k];
                Vss[k] = fma2(s0, s0, fma2(s1, s1, mul2(s2, s2)));
                Vdd[k] = fma2(d0, d0, fma2(d1, d1, mul2(d2, d2)));
            }
            hsum8(Vss[0], Vss[1], Vss[2], Vss[3], vHss, lane, half,
                  Hss[0], Hss[1], Hss[2], Hss[3]);
            hsum8(Vdd[0], Vdd[1], Vdd[2], Vdd[3], vHdd, lane, half,
                  Hdd[0], Hdd[1], Hdd[2], Hdd[3]);
#pragma unroll
            for (int k = 0; k < 4; ++k) {
                u64 N1 = add2(T1[k], kC1);
                u64 D1 = add2(T2[k], kC1);
                u64 U1 = fma2(Hdd[k], km1, Hss[k]);    // Wss - Wdd
                u64 U2 = add2(Hss[k], Hdd[k]);
                u64 N2 = fma2(T1[k], km1, fma2(U1, k9, kC2));
                u64 D2 = fma2(T2[k], km1, fma2(U2, k9, kC2));
                u64 num = mul2(N1, N2);
                u64 den = fma2(D1, D2, kEPS);
                float n0, n1, d0, d1;
                f2_unpack(num, n0, n1);
                f2_unpack(den, d0, d1);
                sAcc += __fdividef(n0, d0);
                sAcc += __fdividef(n1, d1);
            }
        }

        // ---- MSE on the center row (input row R0+r = slot j1) ----
        mAcc0 = fma2(wdv[j1][0], wdv[j1][0], mAcc0);
        mAcc0 = fma2(wdv[j1][1], wdv[j1][1], mAcc0);
        mAcc1 = fma2(wdv[j1][2], wdv[j1][2], mAcc1);
        mAcc1 = fma2(wdv[j1][3], wdv[j1][3], mAcc1);
    }

    cp_wait<0>();   // drain any remaining (empty) groups before exit

    // ---- reductions ----
    float m0, m1, m2, m3;
    f2_unpack(mAcc0, m0, m1);
    f2_unpack(mAcc1, m2, m3);
    float mAcc = (m0 + m1) + (m2 + m3);
#pragma unroll
    for (int o = 16; o; o >>= 1) {
        mAcc += __shfl_xor_sync(0xffffffffu, mAcc, o);
        sAcc += __shfl_xor_sync(0xffffffffu, sAcc, o);
    }
    __shared__ float shm[WPB], shs[WPB];
    if (lane == 0) { shm[w] = mAcc; shs[w] = sAcc; }
    __syncthreads();
    if (threadIdx.x == 0) {
        float M = (shm[0] + shm[1]) + (shm[2] + shm[3]);
        float S = (shs[0] + shs[1]) + (shs[2] + shs[3]);
        atomicAdd(&g_mse_acc, M);
        atomicAdd(&g_ssim_acc, S);
        __threadfence();
        unsigned c = atomicInc(&g_cnt, NBLOCKS - 1);   // wraps to 0 on last
        if (c == NBLOCKS - 1) {
            __threadfence();
            float Mt = atomicExch(&g_mse_acc, 0.f);
            float St = atomicExch(&g_ssim_acc, 0.f);
            double mse  = (double)Mt / NTOTD;
            double ssim = (double)St / NTOTD;
            out[0] = (float)(0.8 * mse + 0.2 * (1.0 - ssim));
        }
    }
}

extern "C" void kernel_launch(void* const* d_in, const int* in_sizes, int n_in,
                              void* d_out, int out_size) {
    const float* X = (const float*)d_in[0];
    const float* Y = (const float*)d_in[1];
    loss_fused<<<NBLOCKS, 128>>>(X, Y, (float*)d_out);
}

// round 7
// speedup vs baseline: 1.0371x; 1.0371x over previous
#include <cuda_runtime.h>

// ---------------------------------------------------------------------------
// EnhancedReconstructionLoss: 0.8*MSE + 0.2*(1 - mean(SSIM_map)), fused.
//
// s/d reformulation (s=x+y, d=x-y) -> 4 window sums (Ws,Wd,Wss,Wdd):
//   N1 = (Ws^2-Wd^2) + 162*C1          N2 = 9(Wss-Wdd) - (Ws^2-Wd^2) + 162*C2
//   D1 = (Ws^2+Wd^2) + 162*C1          D2 = 9(Wss+Wdd) - (Ws^2+Wd^2) + 162*C2
//   ssim = N1*N2 / (D1*D2 + 4*6561*eps)
//
// R7: R4 body (3-slot rolling window, 96 regs, 5 CTAs/SM) + per-lane
// prefetch.global.L2 hints at distance 2 rows. Latency cover with zero
// register cost and ~3 extra instructions per iteration: demand LDGs hit L2
// (~250cyc) instead of DRAM (~600cyc).
// ---------------------------------------------------------------------------

typedef unsigned long long u64;

#define IMW 512
#define IMH 512
#define NPLANES 96
#define RPW 16                    // rows per warp-task
#define STRIPS 32                 // 512 / 16
#define WPB 4                     // warps per block
#define NBLOCKS (NPLANES * STRIPS * 2 / WPB)   // 1536
#define NTOTD 25165824.0          // 32*3*512*512

__device__ float g_mse_acc  = 0.f;
__device__ float g_ssim_acc = 0.f;
__device__ unsigned int g_cnt = 0u;

__device__ __forceinline__ u64 f2_pack(float lo, float hi) {
    u64 r; asm("mov.b64 %0, {%1, %2};" : "=l"(r) : "f"(lo), "f"(hi)); return r;
}
__device__ __forceinline__ void f2_unpack(u64 p, float& lo, float& hi) {
    asm("mov.b64 {%0, %1}, %2;" : "=f"(lo), "=f"(hi) : "l"(p));
}
__device__ __forceinline__ u64 f2_set(float v) { return f2_pack(v, v); }
__device__ __forceinline__ u64 add2(u64 a, u64 b) {
    u64 d; asm("add.rn.f32x2 %0, %1, %2;" : "=l"(d) : "l"(a), "l"(b)); return d;
}
__device__ __forceinline__ u64 mul2(u64 a, u64 b) {
    u64 d; asm("mul.rn.f32x2 %0, %1, %2;" : "=l"(d) : "l"(a), "l"(b)); return d;
}
__device__ __forceinline__ u64 fma2(u64 a, u64 b, u64 c) {
    u64 d; asm("fma.rn.f32x2 %0, %1, %2, %3;" : "=l"(d) : "l"(a), "l"(b), "l"(c)); return d;
}

// Horizontal 3-sum over 8 columns (4 packed u64), warp-shuffle neighbors plus
// scalar halo vH at the warp's interior boundary.
// half==0: cols [0,256) -> left edge is pad(0), right neighbor needs vH.
// half==1: cols [256,512) -> left needs vH, right edge is pad(0).
__device__ __forceinline__ void hsum8(const u64 v0, const u64 v1, const u64 v2, const u64 v3,
                                      float vH, int lane, int half,
                                      u64& H0, u64& H1, u64& H2, u64& H3) {
    float f0, f1, f2, f3, f4, f5, f6, f7;
    f2_unpack(v0, f0, f1);
    f2_unpack(v1, f2, f3);
    f2_unpack(v2, f4, f5);
    f2_unpack(v3, f6, f7);
    float up = __shfl_up_sync(0xffffffffu, f7, 1);
    float dn = __shfl_down_sync(0xffffffffu, f0, 1);
    float nl = (lane == 0)  ? (half ? vH : 0.f) : up;
    float nr = (lane == 31) ? (half ? 0.f : vH) : dn;
    u64 L0 = f2_pack(nl, f0);
    u64 L1 = f2_pack(f1, f2);
    u64 L2 = f2_pack(f3, f4);
    u64 L3 = f2_pack(f5, f6);
    u64 R3 = f2_pack(f7, nr);
    H0 = add2(add2(L0, v0), L1);
    H1 = add2(add2(L1, v1), L2);
    H2 = add2(add2(L2, v2), L3);
    H3 = add2(add2(L3, v3), R3);
}

__global__ void __launch_bounds__(128, 5)
loss_fused(const float* __restrict__ X, const float* __restrict__ Y,
           float* __restrict__ out) {
    const int w    = threadIdx.x >> 5;
    const int lane = threadIdx.x & 31;
    const int task  = blockIdx.x * WPB + w;
    const int half  = task & 1;
    const int strip = (task >> 1) & (STRIPS - 1);
    const int plane = task >> 6;
    const int R0 = strip * RPW;
    const int c0 = half * 256 + (lane << 3);

    const float* px = X + (size_t)plane * (IMW * IMH) + c0;
    const float* py = Y + (size_t)plane * (IMW * IMH) + c0;

    const bool hval = (lane == 0) ? (half == 1)
                    : ((lane == 31) ? (half == 0) : false);
    const int hoff = (lane == 0) ? -1 : 8;

    const u64 km1  = f2_set(-1.0f);
    const u64 k9   = f2_set(9.0f);
    const u64 kC1  = f2_set(0.0162f);      // 162 * C1
    const u64 kC2  = f2_set(0.1458f);      // 162 * C2
    const u64 kEPS = f2_set(2.6244e-4f);   // 4 * 6561 * eps

    // 3-slot rolling window of s,d rows (8 cols = 4 u64 each) + halo scalars.
    u64 ws[3][4], wdv[3][4];
    float whs[3], whd[3];

    // L2 prefetch hint for window row j (zero registers, per-lane 32B span).
    auto PF = [&](int j) {
        int gr = R0 - 1 + j;
        gr = (gr < IMH) ? gr : (IMH - 1);          // clamp (j>=2 so gr>=1)
        const float* ax = px + (size_t)gr * IMW;
        const float* ay = py + (size_t)gr * IMW;
        asm volatile("prefetch.global.L2 [%0];" :: "l"(ax));
        asm volatile("prefetch.global.L2 [%0];" :: "l"(ay));
    };

    // Load input row gr = R0-1+j into slot j%3 (zeros outside the image).
    auto LOAD = [&](int j) {
        const int slot = j % 3;
        const int gr = R0 - 1 + j;
        const bool v = ((unsigned)gr < (unsigned)IMH);
        float4 xa = make_float4(0.f, 0.f, 0.f, 0.f), xb = xa, ya = xa, yb = xa;
        if (v) {
            const float4* p4 = reinterpret_cast<const float4*>(px + (size_t)gr * IMW);
            const float4* q4 = reinterpret_cast<const float4*>(py + (size_t)gr * IMW);
            xa = p4[0]; xb = p4[1];
            ya = q4[0]; yb = q4[1];
        }
        float hx = 0.f, hy = 0.f;
        if (v && hval) {
            hx = px[(size_t)gr * IMW + hoff];
            hy = py[(size_t)gr * IMW + hoff];
        }
        u64 xp0 = f2_pack(xa.x, xa.y), xp1 = f2_pack(xa.z, xa.w);
        u64 xp2 = f2_pack(xb.x, xb.y), xp3 = f2_pack(xb.z, xb.w);
        u64 yp0 = f2_pack(ya.x, ya.y), yp1 = f2_pack(ya.z, ya.w);
        u64 yp2 = f2_pack(yb.x, yb.y), yp3 = f2_pack(yb.z, yb.w);
        ws[slot][0] = add2(xp0, yp0);   wdv[slot][0] = fma2(yp0, km1, xp0);
        ws[slot][1] = add2(xp1, yp1);   wdv[slot][1] = fma2(yp1, km1, xp1);
        ws[slot][2] = add2(xp2, yp2);   wdv[slot][2] = fma2(yp2, km1, xp2);
        ws[slot][3] = add2(xp3, yp3);   wdv[slot][3] = fma2(yp3, km1, xp3);
        whs[slot] = hx + hy;
        whd[slot] = hx - hy;
    };

    LOAD(0); LOAD(1);
    PF(2); PF(3);                // warm L2 for the first two loop loads

    u64 mAcc0 = f2_set(0.f), mAcc1 = f2_set(0.f);
    float sAcc = 0.f;

#pragma unroll
    for (int r = 0; r < RPW; ++r) {
        LOAD(r + 2);                       // demand load (L2-resident via PF)
        if (r + 4 <= RPW + 1) PF(r + 4);   // hint two rows ahead

        const int j0 = r % 3, j1 = (r + 1) % 3, j2 = (r + 2) % 3;

        // halo vertical sums (consumed only by lanes 0/31)
        float hs0 = whs[j0], hs1 = whs[j1], hs2 = whs[j2];
        float hd0 = whd[j0], hd1 = whd[j1], hd2 = whd[j2];
        float vHs  = hs0 + hs1 + hs2;
        float vHd  = hd0 + hd1 + hd2;
        float vHss = fmaf(hs0, hs0, fmaf(hs1, hs1, hs2 * hs2));
        float vHdd = fmaf(hd0, hd0, fmaf(hd1, hd1, hd2 * hd2));

        // ---- Ws, Wd first; derive T1/T2; release transients early ----
        u64 T1[4], T2[4];
        {
            u64 Vq[4], Hq[4];
#pragma unroll
            for (int k = 0; k < 4; ++k)
                Vq[k] = add2(add2(ws[j0][k], ws[j1][k]), ws[j2][k]);
            hsum8(Vq[0], Vq[1], Vq[2], Vq[3], vHs, lane, half,
                  Hq[0], Hq[1], Hq[2], Hq[3]);
            u64 Es[4];
#pragma unroll
            for (int k = 0; k < 4; ++k) Es[k] = mul2(Hq[k], Hq[k]);   // Ws^2
#pragma unroll
            for (int k = 0; k < 4; ++k)
                Vq[k] = add2(add2(wdv[j0][k], wdv[j1][k]), wdv[j2][k]);
            hsum8(Vq[0], Vq[1], Vq[2], Vq[3], vHd, lane, half,
                  Hq[0], Hq[1], Hq[2], Hq[3]);
#pragma unroll
            for (int k = 0; k < 4; ++k) {
                u64 F = mul2(Hq[k], Hq[k]);            // Wd^2
                T1[k] = fma2(F, km1, Es[k]);           // Ws^2 - Wd^2
                T2[k] = add2(Es[k], F);                // Ws^2 + Wd^2
            }
        }

        // ---- Wss, Wdd; finish the rational ----
        {
            u64 Vss[4], Vdd[4], Hss[4], Hdd[4];
#pragma unroll
            for (int k = 0; k < 4; ++k) {
                u64 s0 = ws[j0][k], s1 = ws[j1][k], s2 = ws[j2][k];
                Vss[k] = fma2(s0, s0, fma2(s1, s1, mul2(s2, s2)));
            }
            hsum8(Vss[0], Vss[1], Vss[2], Vss[3], vHss, lane, half,
                  Hss[0], Hss[1], Hss[2], Hss[3]);
#pragma unroll
            for (int k = 0; k < 4; ++k) {
                u64 d0 = wdv[j0][k], d1 = wdv[j1][k], d2 = wdv[j2][k];
                Vdd[k] = fma2(d0, d0, fma2(d1, d1, mul2(d2, d2)));
            }
            hsum8(Vdd[0], Vdd[1], Vdd[2], Vdd[3], vHdd, lane, half,
                  Hdd[0], Hdd[1], Hdd[2], Hdd[3]);
#pragma unroll
            for (int k = 0; k < 4; ++k) {
                u64 N1 = add2(T1[k], kC1);
                u64 D1 = add2(T2[k], kC1);
                u64 U1 = fma2(Hdd[k], km1, Hss[k]);    // Wss - Wdd
                u64 U2 = add2(Hss[k], Hdd[k]);
                u64 N2 = fma2(T1[k], km1, fma2(U1, k9, kC2));
                u64 D2 = fma2(T2[k], km1, fma2(U2, k9, kC2));
                u64 num = mul2(N1, N2);
                u64 den = fma2(D1, D2, kEPS);
                float n0, n1, d0, d1;
                f2_unpack(num, n0, n1);
                f2_unpack(den, d0, d1);
                sAcc += __fdividef(n0, d0);
                sAcc += __fdividef(n1, d1);
            }
        }

        // ---- MSE on the center row (input row R0+r = slot j1) ----
        mAcc0 = fma2(wdv[j1][0], wdv[j1][0], mAcc0);
        mAcc0 = fma2(wdv[j1][1], wdv[j1][1], mAcc0);
        mAcc1 = fma2(wdv[j1][2], wdv[j1][2], mAcc1);
        mAcc1 = fma2(wdv[j1][3], wdv[j1][3], mAcc1);
    }

    // ---- reductions ----
    float m0, m1, m2, m3;
    f2_unpack(mAcc0, m0, m1);
    f2_unpack(mAcc1, m2, m3);
    float mAcc = (m0 + m1) + (m2 + m3);
#pragma unroll
    for (int o = 16; o; o >>= 1) {
        mAcc += __shfl_xor_sync(0xffffffffu, mAcc, o);
        sAcc += __shfl_xor_sync(0xffffffffu, sAcc, o);
    }
    __shared__ float shm[WPB], shs[WPB];
    if (lane == 0) { shm[w] = mAcc; shs[w] = sAcc; }
    __syncthreads();
    if (threadIdx.x == 0) {
        float M = (shm[0] + shm[1]) + (shm[2] + shm[3]);
        float S = (shs[0] + shs[1]) + (shs[2] + shs[3]);
        atomicAdd(&g_mse_acc, M);
        atomicAdd(&g_ssim_acc, S);
        __threadfence();
        unsigned c = atomicInc(&g_cnt, NBLOCKS - 1);   // wraps to 0 on last
        if (c == NBLOCKS - 1) {
            __threadfence();
            float Mt = atomicExch(&g_mse_acc, 0.f);
            float St = atomicExch(&g_ssim_acc, 0.f);
            double mse  = (double)Mt / NTOTD;
            double ssim = (double)St / NTOTD;
            out[0] = (float)(0.8 * mse + 0.2 * (1.0 - ssim));
        }
    }
}

extern "C" void kernel_launch(void* const* d_in, const int* in_sizes, int n_in,
                              void* d_out, int out_size) {
    const float* X = (const float*)d_in[0];
    const float* Y = (const float*)d_in[1];
    loss_fused<<<NBLOCKS, 128>>>(X, Y, (float*)d_out);
}

// round 8
// speedup vs baseline: 1.0835x; 1.0447x over previous
#include <cuda_runtime.h>

// ---------------------------------------------------------------------------
// EnhancedReconstructionLoss: 0.8*MSE + 0.2*(1 - mean(SSIM_map)), fused.
//
// s/d reformulation (s=x+y, d=x-y) -> 4 window sums (Ws,Wd,Wss,Wdd):
//   N1 = (Ws^2-Wd^2) + 162*C1          N2 = 9(Wss-Wdd) - (Ws^2-Wd^2) + 162*C2
//   D1 = (Ws^2+Wd^2) + 162*C1          D2 = 9(Wss+Wdd) - (Ws^2+Wd^2) + 162*C2
//   ssim = N1*N2 / (D1*D2 + 4*6561*eps)
//
// R8 = R5 + L2 prefetch hints, composed:
//   - register prefetch buffer (distance 1) hides L2->reg latency (~250cyc)
//   - prefetch.global.L2 (distance 3) hides DRAM->L2 latency, zero registers
// ---------------------------------------------------------------------------

typedef unsigned long long u64;

#define IMW 512
#define IMH 512
#define NPLANES 96
#define RPW 16                    // rows per warp-task
#define STRIPS 32                 // 512 / 16
#define WPB 4                     // warps per block
#define NBLOCKS (NPLANES * STRIPS * 2 / WPB)   // 1536
#define NTOTD 25165824.0          // 32*3*512*512

__device__ float g_mse_acc  = 0.f;
__device__ float g_ssim_acc = 0.f;
__device__ unsigned int g_cnt = 0u;

__device__ __forceinline__ u64 f2_pack(float lo, float hi) {
    u64 r; asm("mov.b64 %0, {%1, %2};" : "=l"(r) : "f"(lo), "f"(hi)); return r;
}
__device__ __forceinline__ void f2_unpack(u64 p, float& lo, float& hi) {
    asm("mov.b64 {%0, %1}, %2;" : "=f"(lo), "=f"(hi) : "l"(p));
}
__device__ __forceinline__ u64 f2_set(float v) { return f2_pack(v, v); }
__device__ __forceinline__ u64 add2(u64 a, u64 b) {
    u64 d; asm("add.rn.f32x2 %0, %1, %2;" : "=l"(d) : "l"(a), "l"(b)); return d;
}
__device__ __forceinline__ u64 mul2(u64 a, u64 b) {
    u64 d; asm("mul.rn.f32x2 %0, %1, %2;" : "=l"(d) : "l"(a), "l"(b)); return d;
}
__device__ __forceinline__ u64 fma2(u64 a, u64 b, u64 c) {
    u64 d; asm("fma.rn.f32x2 %0, %1, %2, %3;" : "=l"(d) : "l"(a), "l"(b), "l"(c)); return d;
}

// Horizontal 3-sum over 8 columns (4 packed u64), warp-shuffle neighbors plus
// scalar halo vH at the warp's interior boundary.
__device__ __forceinline__ void hsum8(const u64 v0, const u64 v1, const u64 v2, const u64 v3,
                                      float vH, int lane, int half,
                                      u64& H0, u64& H1, u64& H2, u64& H3) {
    float f0, f1, f2, f3, f4, f5, f6, f7;
    f2_unpack(v0, f0, f1);
    f2_unpack(v1, f2, f3);
    f2_unpack(v2, f4, f5);
    f2_unpack(v3, f6, f7);
    float up = __shfl_up_sync(0xffffffffu, f7, 1);
    float dn = __shfl_down_sync(0xffffffffu, f0, 1);
    float nl = (lane == 0)  ? (half ? vH : 0.f) : up;
    float nr = (lane == 31) ? (half ? 0.f : vH) : dn;
    u64 L0 = f2_pack(nl, f0);
    u64 L1 = f2_pack(f1, f2);
    u64 L2 = f2_pack(f3, f4);
    u64 L3 = f2_pack(f5, f6);
    u64 R3 = f2_pack(f7, nr);
    H0 = add2(add2(L0, v0), L1);
    H1 = add2(add2(L1, v1), L2);
    H2 = add2(add2(L2, v2), L3);
    H3 = add2(add2(L3, v3), R3);
}

__global__ void __launch_bounds__(128, 4)
loss_fused(const float* __restrict__ X, const float* __restrict__ Y,
           float* __restrict__ out) {
    const int w    = threadIdx.x >> 5;
    const int lane = threadIdx.x & 31;
    const int task  = blockIdx.x * WPB + w;
    const int half  = task & 1;
    const int strip = (task >> 1) & (STRIPS - 1);
    const int plane = task >> 6;
    const int R0 = strip * RPW;
    const int c0 = half * 256 + (lane << 3);

    const float* px = X + (size_t)plane * (IMW * IMH) + c0;
    const float* py = Y + (size_t)plane * (IMW * IMH) + c0;

    const bool hval = (lane == 0) ? (half == 1)
                    : ((lane == 31) ? (half == 0) : false);
    const int hoff = (lane == 0) ? -1 : 8;

    const u64 km1  = f2_set(-1.0f);
    const u64 k9   = f2_set(9.0f);
    const u64 kC1  = f2_set(0.0162f);      // 162 * C1
    const u64 kC2  = f2_set(0.1458f);      // 162 * C2
    const u64 kEPS = f2_set(2.6244e-4f);   // 4 * 6561 * eps

    // 3-slot rolling window of s,d rows (8 cols = 4 u64 each) + halo scalars.
    u64 ws[3][4], wdv[3][4];
    float whs[3], whd[3];

    // Distance-1 register prefetch buffer (raw loads for the NEXT window row).
    float4 pxa, pxb, pya, pyb;
    float phx, phy;

    // L2 prefetch hint for window row j (zero registers).
    auto PF = [&](int j) {
        int gr = R0 - 1 + j;
        gr = (gr < IMH) ? gr : (IMH - 1);   // clamp; only hints
        const float* ax = px + (size_t)gr * IMW;
        const float* ay = py + (size_t)gr * IMW;
        asm volatile("prefetch.global.L2 [%0];" :: "l"(ax));
        asm volatile("prefetch.global.L2 [%0];" :: "l"(ay));
    };

    // Issue loads of input row gr = R0-1+j into the register prefetch buffer.
    auto PREFETCH = [&](int j) {
        const int gr = R0 - 1 + j;
        const bool v = ((unsigned)gr < (unsigned)IMH);
        pxa = make_float4(0.f, 0.f, 0.f, 0.f); pxb = pxa; pya = pxa; pyb = pxa;
        phx = 0.f; phy = 0.f;
        if (v) {
            const float4* p4 = reinterpret_cast<const float4*>(px + (size_t)gr * IMW);
            const float4* q4 = reinterpret_cast<const float4*>(py + (size_t)gr * IMW);
            pxa = p4[0]; pxb = p4[1];
            pya = q4[0]; pyb = q4[1];
            if (hval) {
                phx = px[(size_t)gr * IMW + hoff];
                phy = py[(size_t)gr * IMW + hoff];
            }
        }
    };

    // Convert the prefetch buffer into window slot j%3.
    auto CONVERT = [&](int j) {
        const int slot = j % 3;
        u64 xp0 = f2_pack(pxa.x, pxa.y), xp1 = f2_pack(pxa.z, pxa.w);
        u64 xp2 = f2_pack(pxb.x, pxb.y), xp3 = f2_pack(pxb.z, pxb.w);
        u64 yp0 = f2_pack(pya.x, pya.y), yp1 = f2_pack(pya.z, pya.w);
        u64 yp2 = f2_pack(pyb.x, pyb.y), yp3 = f2_pack(pyb.z, pyb.w);
        ws[slot][0] = add2(xp0, yp0);   wdv[slot][0] = fma2(yp0, km1, xp0);
        ws[slot][1] = add2(xp1, yp1);   wdv[slot][1] = fma2(yp1, km1, xp1);
        ws[slot][2] = add2(xp2, yp2);   wdv[slot][2] = fma2(yp2, km1, xp2);
        ws[slot][3] = add2(xp3, yp3);   wdv[slot][3] = fma2(yp3, km1, xp3);
        whs[slot] = phx + phy;
        whd[slot] = phx - phy;
    };

    // Prologue: hint rows 2..4 into L2, then prime the register pipeline.
    PF(2); PF(3); PF(4);
    PREFETCH(0); CONVERT(0);
    PREFETCH(1); CONVERT(1);
    PREFETCH(2);                       // row 2 in flight entering the loop

    u64 mAcc0 = f2_set(0.f), mAcc1 = f2_set(0.f);
    float sAcc = 0.f;

#pragma unroll
    for (int r = 0; r < RPW; ++r) {
        CONVERT(r + 2);                     // consume row loaded last iteration
        if (r < RPW - 1) PREFETCH(r + 3);   // LDG (hits L2 thanks to PF)
        if (r + 5 <= RPW + 1) PF(r + 5);    // hint DRAM->L2 three rows ahead

        const int j0 = r % 3, j1 = (r + 1) % 3, j2 = (r + 2) % 3;

        // halo vertical sums (consumed only by lanes 0/31)
        float hs0 = whs[j0], hs1 = whs[j1], hs2 = whs[j2];
        float hd0 = whd[j0], hd1 = whd[j1], hd2 = whd[j2];
        float vHs  = hs0 + hs1 + hs2;
        float vHd  = hd0 + hd1 + hd2;
        float vHss = fmaf(hs0, hs0, fmaf(hs1, hs1, hs2 * hs2));
        float vHdd = fmaf(hd0, hd0, fmaf(hd1, hd1, hd2 * hd2));

        // ---- Ws, Wd first; derive T1/T2; release transients early ----
        u64 T1[4], T2[4];
        {
            u64 Vq[4], Hq[4];
#pragma unroll
            for (int k = 0; k < 4; ++k)
                Vq[k] = add2(add2(ws[j0][k], ws[j1][k]), ws[j2][k]);
            hsum8(Vq[0], Vq[1], Vq[2], Vq[3], vHs, lane, half,
                  Hq[0], Hq[1], Hq[2], Hq[3]);
            u64 Es[4];
#pragma unroll
            for (int k = 0; k < 4; ++k) Es[k] = mul2(Hq[k], Hq[k]);   // Ws^2
#pragma unroll
            for (int k = 0; k < 4; ++k)
                Vq[k] = add2(add2(wdv[j0][k], wdv[j1][k]), wdv[j2][k]);
            hsum8(Vq[0], Vq[1], Vq[2], Vq[3], vHd, lane, half,
                  Hq[0], Hq[1], Hq[2], Hq[3]);
#pragma unroll
            for (int k = 0; k < 4; ++k) {
                u64 F = mul2(Hq[k], Hq[k]);            // Wd^2
                T1[k] = fma2(F, km1, Es[k]);           // Ws^2 - Wd^2
                T2[k] = add2(Es[k], F);                // Ws^2 + Wd^2
            }
        }

        // ---- Wss, Wdd; finish the rational ----
        {
            u64 Vss[4], Vdd[4], Hss[4], Hdd[4];
#pragma unroll
            for (int k = 0; k < 4; ++k) {
                u64 s0 = ws[j0][k], s1 = ws[j1][k], s2 = ws[j2][k];
                Vss[k] = fma2(s0, s0, fma2(s1, s1, mul2(s2, s2)));
            }
            hsum8(Vss[0], Vss[1], Vss[2], Vss[3], vHss, lane, half,
                  Hss[0], Hss[1], Hss[2], Hss[3]);
#pragma unroll
            for (int k = 0; k < 4; ++k) {
                u64 d0 = wdv[j0][k], d1 = wdv[j1][k], d2 = wdv[j2][k];
                Vdd[k] = fma2(d0, d0, fma2(d1, d1, mul2(d2, d2)));
            }
            hsum8(Vdd[0], Vdd[1], Vdd[2], Vdd[3], vHdd, lane, half,
                  Hdd[0], Hdd[1], Hdd[2], Hdd[3]);
#pragma unroll
            for (int k = 0; k < 4; ++k) {
                u64 N1 = add2(T1[k], kC1);
                u64 D1 = add2(T2[k], kC1);
                u64 U1 = fma2(Hdd[k], km1, Hss[k]);    // Wss - Wdd
                u64 U2 = add2(Hss[k], Hdd[k]);
                u64 N2 = fma2(T1[k], km1, fma2(U1, k9, kC2));
                u64 D2 = fma2(T2[k], km1, fma2(U2, k9, kC2));
                u64 num = mul2(N1, N2);
                u64 den = fma2(D1, D2, kEPS);
                float n0, n1, d0, d1;
                f2_unpack(num, n0, n1);
                f2_unpack(den, d0, d1);
                sAcc += __fdividef(n0, d0);
                sAcc += __fdividef(n1, d1);
            }
        }

        // ---- MSE on the center row (input row R0+r = slot j1) ----
        mAcc0 = fma2(wdv[j1][0], wdv[j1][0], mAcc0);
        mAcc0 = fma2(wdv[j1][1], wdv[j1][1], mAcc0);
        mAcc1 = fma2(wdv[j1][2], wdv[j1][2], mAcc1);
        mAcc1 = fma2(wdv[j1][3], wdv[j1][3], mAcc1);
    }

    // ---- reductions ----
    float m0, m1, m2, m3;
    f2_unpack(mAcc0, m0, m1);
    f2_unpack(mAcc1, m2, m3);
    float mAcc = (m0 + m1) + (m2 + m3);
#pragma unroll
    for (int o = 16; o; o >>= 1) {
        mAcc += __shfl_xor_sync(0xffffffffu, mAcc, o);
        sAcc += __shfl_xor_sync(0xffffffffu, sAcc, o);
    }
    __shared__ float shm[WPB], shs[WPB];
    if (lane == 0) { shm[w] = mAcc; shs[w] = sAcc; }
    __syncthreads();
    if (threadIdx.x == 0) {
        float M = (shm[0] + shm[1]) + (shm[2] + shm[3]);
        float S = (shs[0] + shs[1]) + (shs[2] + shs[3]);
        atomicAdd(&g_mse_acc, M);
        atomicAdd(&g_ssim_acc, S);
        __threadfence();
        unsigned c = atomicInc(&g_cnt, NBLOCKS - 1);   // wraps to 0 on last
        if (c == NBLOCKS - 1) {
            __threadfence();
            float Mt = atomicExch(&g_mse_acc, 0.f);
            float St = atomicExch(&g_ssim_acc, 0.f);
            double mse  = (double)Mt / NTOTD;
            double ssim = (double)St / NTOTD;
            out[0] = (float)(0.8 * mse + 0.2 * (1.0 - ssim));
        }
    }
}

extern "C" void kernel_launch(void* const* d_in, const int* in_sizes, int n_in,
                              void* d_out, int out_size) {
    const float* X = (const float*)d_in[0];
    const float* Y = (const float*)d_in[1];
    loss_fused<<<NBLOCKS, 128>>>(X, Y, (float*)d_out);
}